// round 15
// baseline (speedup 1.0000x reference)
#include <cuda_runtime.h>
#include <cuda_bf16.h>
#include <cuda_fp16.h>
#include <cstdint>

// ---------------------------------------------------------------------------
// GraphSAGE: 3x (SAGEConv mean-aggr -> LayerNorm -> ReLU), mean|max pool, MLP.
//
//   y = x @ [Wl^T | Wr^T]   split-bf16 tensor GEMM: y = xh@Wh + xl@Wh + xh@Wlo
//   (mma.sync.m16n8k16 bf16 -> HMMA; tcgen05 unavailable: plain sm_103 target)
//   h = relu(LN( mean_{j in N(i)} yl[j] + bl + yr[i] ) * g + be)
// PADDED CSR (stride 64): one atomic-slot scatter; no count pass, no scan.
// Aggregation: 2 nodes/warp, 16 lanes/node, uint4 fp16 gathers (2 rows/instr).
// GEMM epilogue: yl stored FP16, yr FP32. edge_index/batch are INT32.
// kernel_launch contains ONLY kernel launches; static smem <= 48 KB.
// ---------------------------------------------------------------------------

#define NGRAPH 64
#define DEGS   64

// ------------------------- device scratch (static) -------------------------
__device__ __align__(16) __half g_ylh[50048 * 128];
__device__ __align__(16) float  g_yr [50048 * 128];
__device__ __align__(16) float  g_h1 [50048 * 128];
__device__ __align__(16) float  g_h2 [50048 * 128];
__device__ int g_deg [50048];
__device__ int g_colp[50048 * DEGS];
// Weights in mma.sync B-FRAGMENT order (bf16 hi / lo residual):
// u = ((((k16*NT8 + ntile)*32 + lane)*2 + reg)*2 + elem)
__device__ __align__(16) __nv_bfloat16 g_wh0 [256 * 128];
__device__ __align__(16) __nv_bfloat16 g_wlo0[256 * 128];
__device__ __align__(16) __nv_bfloat16 g_wh1 [256 * 128];
__device__ __align__(16) __nv_bfloat16 g_wlo1[256 * 128];
__device__ __align__(16) __nv_bfloat16 g_wh2 [128 * 128];
__device__ __align__(16) __nv_bfloat16 g_wlo2[128 * 128];

// ------------------------------ small helpers ------------------------------
__device__ __forceinline__ uint32_t pack2bf(__nv_bfloat16 a, __nv_bfloat16 b) {
    __nv_bfloat162 t;
    t.x = a; t.y = b;
    return *reinterpret_cast<uint32_t*>(&t);
}

__device__ __forceinline__ void mma16816(float* d, const uint32_t* a,
                                         const uint32_t* b) {
    asm volatile(
        "mma.sync.aligned.m16n8k16.row.col.f32.bf16.bf16.f32 "
        "{%0,%1,%2,%3}, {%4,%5,%6,%7}, {%8,%9}, {%0,%1,%2,%3};"
        : "+f"(d[0]), "+f"(d[1]), "+f"(d[2]), "+f"(d[3])
        : "r"(a[0]), "r"(a[1]), "r"(a[2]), "r"(a[3]), "r"(b[0]), "r"(b[1]));
}

// ------------------------------ preprocessing ------------------------------
__global__ void scatter_pad_kernel(const int* __restrict__ ei, int E) {
    int e = blockIdx.x * blockDim.x + threadIdx.x;
    if (e < E) {
        int sN = ei[e];
        int d  = ei[E + e];
        int p  = atomicAdd(&g_deg[d], 1);
        if (p < DEGS) g_colp[d * DEGS + p] = sN;
    }
}

// All three weight splits in ONE kernel (+ zero g_deg).
__global__ void wconv_all_kernel(const float* __restrict__ Wl0, const float* __restrict__ Wr0,
                                 const float* __restrict__ Wl1, const float* __restrict__ Wr1,
                                 const float* __restrict__ Wl2, const float* __restrict__ Wr2) {
    for (int i = blockIdx.x * blockDim.x + threadIdx.x; i < 50048;
         i += gridDim.x * blockDim.x)
        g_deg[i] = 0;

    const int total = 32768 + 32768 + 16384;    // F2*128 per layer
    for (int idx = blockIdx.x * blockDim.x + threadIdx.x; idx < total;
         idx += gridDim.x * blockDim.x) {
        const float *Wl, *Wr;
        __nv_bfloat16 *WH, *WO;
        int off, F;
        if (idx < 32768)      { off = idx;          F = 128; Wl = Wl0; Wr = Wr0; WH = g_wh0; WO = g_wlo0; }
        else if (idx < 65536) { off = idx - 32768;  F = 128; Wl = Wl1; Wr = Wr1; WH = g_wh1; WO = g_wlo1; }
        else                  { off = idx - 65536;  F = 64;  Wl = Wl2; Wr = Wr2; WH = g_wh2; WO = g_wlo2; }
        int F2 = 2 * F, NT8 = F2 / 8;
        int o = off >> 7;
        int k = off & 127;
        float v = (o < F) ? Wl[o * 128 + k] : Wr[(o - F) * 128 + k];
        __nv_bfloat16 h = __float2bfloat16(v);
        __nv_bfloat16 l = __float2bfloat16(v - __bfloat162float(h));
        int k16 = k >> 4, kin = k & 15;
        int reg = kin >> 3, tq = (kin >> 1) & 3, elem = kin & 1;
        int lane = (o & 7) * 4 + tq;
        int u = ((((k16 * NT8 + (o >> 3)) * 32 + lane) * 2 + reg) * 2 + elem);
        WH[u] = h;
        WO[u] = l;
    }
}

// ---------------------- tensor-core dense GEMM (HMMA) ----------------------
template <int F2, int XSEL, int WSEL>
__global__ void __launch_bounds__(256) tgemm_kernel(const float* __restrict__ Xin,
                                                    int N) {
    constexpr int NT8 = F2 / 8;
    constexpr int WNT = F2 / 32;
    constexpr int F   = F2 / 2;
    constexpr int STR = 136;
    __shared__ __nv_bfloat16 xh[64 * STR];
    __shared__ __nv_bfloat16 xl[64 * STR];

    const float* X = (XSEL == 0) ? Xin : (XSEL == 1) ? g_h1 : g_h2;
    const uint32_t* WH = (const uint32_t*)((WSEL == 0) ? g_wh0  : (WSEL == 1) ? g_wh1  : g_wh2);
    const uint32_t* WO = (const uint32_t*)((WSEL == 0) ? g_wlo0 : (WSEL == 1) ? g_wlo1 : g_wlo2);

    const int tid  = threadIdx.x;
    const int w    = tid >> 5, lane = tid & 31;
    const int gid  = lane >> 2, tq = lane & 3;
    const int bm   = blockIdx.x * 64;
    const int wm   = (w >> 2) * 32;
    const int wn   = (w & 3) * (F2 / 4);
    const int wnt0 = wn >> 3;

#pragma unroll
    for (int i = 0; i < 8; i++) {
        int idx = tid + 256 * i;
        int m = idx >> 5, k4 = idx & 31;
        int row = bm + m;
        float4 v = make_float4(0.f, 0.f, 0.f, 0.f);
        if (row < N) v = *reinterpret_cast<const float4*>(X + (size_t)row * 128 + k4 * 4);
        __nv_bfloat16 h0 = __float2bfloat16(v.x), h1 = __float2bfloat16(v.y);
        __nv_bfloat16 h2 = __float2bfloat16(v.z), h3 = __float2bfloat16(v.w);
        __nv_bfloat16 l0 = __float2bfloat16(v.x - __bfloat162float(h0));
        __nv_bfloat16 l1 = __float2bfloat16(v.y - __bfloat162float(h1));
        __nv_bfloat16 l2 = __float2bfloat16(v.z - __bfloat162float(h2));
        __nv_bfloat16 l3 = __float2bfloat16(v.w - __bfloat162float(h3));
        int eo = m * STR + k4 * 4;
        *reinterpret_cast<uint2*>(&xh[eo]) = make_uint2(pack2bf(h0, h1), pack2bf(h2, h3));
        *reinterpret_cast<uint2*>(&xl[eo]) = make_uint2(pack2bf(l0, l1), pack2bf(l2, l3));
    }
    __syncthreads();

    float acc[2][WNT][4];
#pragma unroll
    for (int s = 0; s < 2; s++)
#pragma unroll
        for (int nt = 0; nt < WNT; nt++)
#pragma unroll
            for (int i = 0; i < 4; i++) acc[s][nt][i] = 0.f;

#pragma unroll
    for (int k16 = 0; k16 < 8; k16++) {
        const int c = k16 * 16 + tq * 2;
        uint32_t ah[2][4], al[2][4];
#pragma unroll
        for (int s = 0; s < 2; s++) {
            int base = (wm + s * 16 + gid) * STR + c;
            ah[s][0] = *reinterpret_cast<const uint32_t*>(&xh[base]);
            ah[s][1] = *reinterpret_cast<const uint32_t*>(&xh[base + 8 * STR]);
            ah[s][2] = *reinterpret_cast<const uint32_t*>(&xh[base + 8]);
            ah[s][3] = *reinterpret_cast<const uint32_t*>(&xh[base + 8 * STR + 8]);
            al[s][0] = *reinterpret_cast<const uint32_t*>(&xl[base]);
            al[s][1] = *reinterpret_cast<const uint32_t*>(&xl[base + 8 * STR]);
            al[s][2] = *reinterpret_cast<const uint32_t*>(&xl[base + 8]);
            al[s][3] = *reinterpret_cast<const uint32_t*>(&xl[base + 8 * STR + 8]);
        }
#pragma unroll
        for (int nt = 0; nt < WNT; nt++) {
            size_t base = ((size_t)(k16 * NT8 + wnt0 + nt) * 32 + lane) * 2;
            uint2 bh = *reinterpret_cast<const uint2*>(WH + base);
            uint2 bo = *reinterpret_cast<const uint2*>(WO + base);
            uint32_t bhv[2] = {bh.x, bh.y};
            uint32_t bov[2] = {bo.x, bo.y};
#pragma unroll
            for (int s = 0; s < 2; s++) {
                mma16816(acc[s][nt], ah[s], bhv);
                mma16816(acc[s][nt], al[s], bhv);
                mma16816(acc[s][nt], ah[s], bov);
            }
        }
    }

#pragma unroll
    for (int s = 0; s < 2; s++) {
        int r0 = bm + wm + s * 16 + gid;
#pragma unroll
        for (int nt = 0; nt < WNT; nt++) {
            int o0 = wn + nt * 8 + tq * 2;
            if (o0 < F) {
                if (r0 < N)
                    *reinterpret_cast<__half2*>(g_ylh + (size_t)r0 * F + o0) =
                        __floats2half2_rn(acc[s][nt][0], acc[s][nt][1]);
                if (r0 + 8 < N)
                    *reinterpret_cast<__half2*>(g_ylh + (size_t)(r0 + 8) * F + o0) =
                        __floats2half2_rn(acc[s][nt][2], acc[s][nt][3]);
            } else {
                if (r0 < N)
                    *reinterpret_cast<float2*>(g_yr + (size_t)r0 * F + o0 - F) =
                        make_float2(acc[s][nt][0], acc[s][nt][1]);
                if (r0 + 8 < N)
                    *reinterpret_cast<float2*>(g_yr + (size_t)(r0 + 8) * F + o0 - F) =
                        make_float2(acc[s][nt][2], acc[s][nt][3]);
            }
        }
    }
}

// ------------------- fused aggregation + LayerNorm + ReLU -------------------
// 2 nodes per warp, 16 lanes per node: one warp LDG serves TWO neighbor rows.
// Half-warp shfl masks keep exchanges legal under divergent degree loops.
template <int F, int OSEL>   // F: 128 or 64; OSEL: 1 -> g_h1, 2 -> g_h2
__global__ void agg_ln_kernel(const float* __restrict__ bl,
                              const float* __restrict__ gm,
                              const float* __restrict__ be, int N) {
    constexpr int VPL = F / 16;        // floats per lane: 8 or 4
    float* Hout = (OSEL == 1) ? g_h1 : g_h2;
    int warp = (blockIdx.x * blockDim.x + threadIdx.x) >> 5;
    int lane = threadIdx.x & 31;
    int half = lane >> 4, hl = lane & 15;
    int d    = warp * 2 + half;
    bool valid = d < N;
    int dc = valid ? d : 0;
    const unsigned HM = 0xFFFFu << (half * 16);

    int deg = g_deg[dc];
    int cap = min(deg, DEGS);

    float acc[4][VPL];
#pragma unroll
    for (int u = 0; u < 4; u++)
#pragma unroll
        for (int i = 0; i < VPL; i++) acc[u][i] = 0.f;

    const __half* Yl = g_ylh;
    for (int c0 = 0; c0 < cap; c0 += 16) {
        int j = 0;
        if (c0 + hl < cap) j = g_colp[dc * DEGS + c0 + hl];
        int cnt = min(cap - c0, 16);
        int t = 0;
        for (; t + 8 <= cnt; t += 8) {
            int jj[8];
#pragma unroll
            for (int u = 0; u < 8; u++) jj[u] = __shfl_sync(HM, j, t + u, 16);
            if (VPL == 8) {
                uint4 q[8];
#pragma unroll
                for (int u = 0; u < 8; u++)
                    q[u] = __ldcg((const uint4*)(Yl + (size_t)jj[u] * F + hl * 8));
#pragma unroll
                for (int u = 0; u < 8; u++) {
                    float2 a = __half22float2(*(__half2*)&q[u].x);
                    float2 b = __half22float2(*(__half2*)&q[u].y);
                    float2 cc = __half22float2(*(__half2*)&q[u].z);
                    float2 dd = __half22float2(*(__half2*)&q[u].w);
                    acc[u & 3][0] += a.x;  acc[u & 3][1] += a.y;
                    acc[u & 3][2] += b.x;  acc[u & 3][3] += b.y;
                    acc[u & 3][4] += cc.x; acc[u & 3][5] += cc.y;
                    acc[u & 3][6] += dd.x; acc[u & 3][7] += dd.y;
                }
            } else {
                uint2 q[8];
#pragma unroll
                for (int u = 0; u < 8; u++)
                    q[u] = __ldcg((const uint2*)(Yl + (size_t)jj[u] * F + hl * 4));
#pragma unroll
                for (int u = 0; u < 8; u++) {
                    float2 a = __half22float2(*(__half2*)&q[u].x);
                    float2 b = __half22float2(*(__half2*)&q[u].y);
                    acc[u & 3][0] += a.x; acc[u & 3][1] += a.y;
                    acc[u & 3][2] += b.x; acc[u & 3][3] += b.y;
                }
            }
        }
        for (; t + 4 <= cnt; t += 4) {
            int jj[4];
#pragma unroll
            for (int u = 0; u < 4; u++) jj[u] = __shfl_sync(HM, j, t + u, 16);
            if (VPL == 8) {
                uint4 q[4];
#pragma unroll
                for (int u = 0; u < 4; u++)
                    q[u] = __ldcg((const uint4*)(Yl + (size_t)jj[u] * F + hl * 8));
#pragma unroll
                for (int u = 0; u < 4; u++) {
                    float2 a = __half22float2(*(__half2*)&q[u].x);
                    float2 b = __half22float2(*(__half2*)&q[u].y);
                    float2 cc = __half22float2(*(__half2*)&q[u].z);
                    float2 dd = __half22float2(*(__half2*)&q[u].w);
                    acc[u][0] += a.x;  acc[u][1] += a.y;
                    acc[u][2] += b.x;  acc[u][3] += b.y;
                    acc[u][4] += cc.x; acc[u][5] += cc.y;
                    acc[u][6] += dd.x; acc[u][7] += dd.y;
                }
            } else {
                uint2 q[4];
#pragma unroll
                for (int u = 0; u < 4; u++)
                    q[u] = __ldcg((const uint2*)(Yl + (size_t)jj[u] * F + hl * 4));
#pragma unroll
                for (int u = 0; u < 4; u++) {
                    float2 a = __half22float2(*(__half2*)&q[u].x);
                    float2 b = __half22float2(*(__half2*)&q[u].y);
                    acc[u][0] += a.x; acc[u][1] += a.y;
                    acc[u][2] += b.x; acc[u][3] += b.y;
                }
            }
        }
        for (; t < cnt; t++) {
            int jj = __shfl_sync(HM, j, t, 16);
            if (VPL == 8) {
                uint4 q = __ldcg((const uint4*)(Yl + (size_t)jj * F + hl * 8));
                float2 a = __half22float2(*(__half2*)&q.x);
                float2 b = __half22float2(*(__half2*)&q.y);
                float2 cc = __half22float2(*(__half2*)&q.z);
                float2 dd = __half22float2(*(__half2*)&q.w);
                acc[0][0] += a.x;  acc[0][1] += a.y;
                acc[0][2] += b.x;  acc[0][3] += b.y;
                acc[0][4] += cc.x; acc[0][5] += cc.y;
                acc[0][6] += dd.x; acc[0][7] += dd.y;
            } else {
                uint2 q = __ldcg((const uint2*)(Yl + (size_t)jj * F + hl * 4));
                float2 a = __half22float2(*(__half2*)&q.x);
                float2 b = __half22float2(*(__half2*)&q.y);
                acc[0][0] += a.x; acc[0][1] += a.y;
                acc[0][2] += b.x; acc[0][3] += b.y;
            }
        }
    }

    float invd = 1.0f / (float)max(deg, 1);
    const float* yr = g_yr + (size_t)dc * F + hl * VPL;
    float v[VPL];
#pragma unroll
    for (int i = 0; i < VPL; i++) {
        float a = (acc[0][i] + acc[1][i]) + (acc[2][i] + acc[3][i]);
        v[i] = a * invd + yr[i] + bl[hl * VPL + i];
    }

    float s = 0.f;
#pragma unroll
    for (int i = 0; i < VPL; i++) s += v[i];
#pragma unroll
    for (int off = 8; off > 0; off >>= 1) s += __shfl_xor_sync(HM, s, off);
    float mu = s * (1.0f / F);

    float q = 0.f;
#pragma unroll
    for (int i = 0; i < VPL; i++) { float dd = v[i] - mu; q += dd * dd; }
#pragma unroll
    for (int off = 8; off > 0; off >>= 1) q += __shfl_xor_sync(HM, q, off);
    float rstd = rsqrtf(q * (1.0f / F) + 1e-5f);

    if (valid) {
        float* out = Hout + (size_t)d * F + hl * VPL;
#pragma unroll
        for (int i = 0; i < VPL; i++) {
            float o = (v[i] - mu) * rstd * gm[hl * VPL + i] + be[hl * VPL + i];
            out[i] = fmaxf(o, 0.f);
        }
    }
}

// ------------------ fused pooling (mean|max) + MLP head ---------------------
__device__ __forceinline__ int lbound32(const int* b, int n, int v) {
    int lo = 0, hi = n;
    while (lo < hi) {
        int mid = (lo + hi) >> 1;
        if (b[mid] < v) lo = mid + 1; else hi = mid;
    }
    return lo;
}

__global__ void poolhead_kernel(const int* __restrict__ batch,
                                const float* __restrict__ cW1, const float* __restrict__ cb1,
                                const float* __restrict__ cW2, const float* __restrict__ cb2,
                                float* __restrict__ out, int N) {
    int g = blockIdx.x;
    int s = lbound32(batch, N, g);
    int e = lbound32(batch, N, g + 1);
    int tid = threadIdx.x;
    int f = tid & 63;
    int r = tid >> 6;
    float sum = 0.f, mx = 0.f;
    for (int i = s + r; i < e; i += 4) {
        float v = g_h1[(size_t)i * 64 + f];
        sum += v;
        mx = fmaxf(mx, v);
    }
    __shared__ float ssum[4][64], smax[4][64], zs[128], s1[128];
    ssum[r][f] = sum;
    smax[r][f] = mx;
    __syncthreads();
    if (r == 0) {
        float S = ssum[0][f] + ssum[1][f] + ssum[2][f] + ssum[3][f];
        float M = fmaxf(fmaxf(smax[0][f], smax[1][f]), fmaxf(smax[2][f], smax[3][f]));
        float invc = 1.0f / (float)max(e - s, 1);
        zs[f]      = S * invc;
        zs[64 + f] = M;
    }
    __syncthreads();
    if (tid < 128) {
        float acc = cb1[tid];
        const float* w = cW1 + tid * 128;
#pragma unroll 8
        for (int k = 0; k < 128; k++) acc += zs[k] * w[k];
        s1[tid] = fmaxf(acc, 0.f);
    }
    __syncthreads();
    if (tid < 2) {
        float a = cb2[tid];
        const float* w2 = cW2 + tid * 128;
        for (int k = 0; k < 128; k++) a += s1[k] * w2[k];
        out[g * 2 + tid] = a;
    }
}

// --------------------------------- launcher ---------------------------------
extern "C" void kernel_launch(void* const* d_in, const int* in_sizes, int n_in,
                              void* d_out, int out_size) {
    const float* x     = (const float*)d_in[0];
    const int*   ei    = (const int*)d_in[1];
    const int*   batch = (const int*)d_in[2];
    const float *Wl0 = (const float*)d_in[3],  *bl0 = (const float*)d_in[4],
                *Wr0 = (const float*)d_in[5],  *g0  = (const float*)d_in[6],
                *be0 = (const float*)d_in[7];
    const float *Wl1 = (const float*)d_in[8],  *bl1 = (const float*)d_in[9],
                *Wr1 = (const float*)d_in[10], *g1  = (const float*)d_in[11],
                *be1 = (const float*)d_in[12];
    const float *Wl2 = (const float*)d_in[13], *bl2 = (const float*)d_in[14],
                *Wr2 = (const float*)d_in[15], *g2  = (const float*)d_in[16],
                *be2 = (const float*)d_in[17];
    const float *cW1 = (const float*)d_in[18], *cb1 = (const float*)d_in[19],
                *cW2 = (const float*)d_in[20], *cb2 = (const float*)d_in[21];
    float* out = (float*)d_out;

    const int N = in_sizes[0] / 128;
    const int E = in_sizes[1] / 2;

    const int tgGrid  = (N + 63) / 64;
    const int aggGrid = (N + 15) / 16;    // 2 nodes/warp, 8 warps/block

    wconv_all_kernel<<<320, 256>>>(Wl0, Wr0, Wl1, Wr1, Wl2, Wr2);
    scatter_pad_kernel<<<(E + 255) / 256, 256>>>(ei, E);
    tgemm_kernel<256, 0, 0><<<tgGrid, 256>>>(x, N);

    agg_ln_kernel<128, 1><<<aggGrid, 256>>>(bl0, g0, be0, N);

    tgemm_kernel<256, 1, 1><<<tgGrid, 256>>>(nullptr, N);
    agg_ln_kernel<128, 2><<<aggGrid, 256>>>(bl1, g1, be1, N);

    tgemm_kernel<128, 2, 2><<<tgGrid, 256>>>(nullptr, N);
    agg_ln_kernel<64, 1><<<aggGrid, 256>>>(bl2, g2, be2, N);

    poolhead_kernel<<<NGRAPH, 256>>>(batch, cW1, cb1, cW2, cb2, out, N);
}

// round 16
// speedup vs baseline: 1.0103x; 1.0103x over previous
#include <cuda_runtime.h>
#include <cuda_bf16.h>
#include <cuda_fp16.h>
#include <cstdint>

// ---------------------------------------------------------------------------
// GraphSAGE: 3x (SAGEConv mean-aggr -> LayerNorm -> ReLU), mean|max pool, MLP.
//
//   y = x @ [Wl^T | Wr^T]   split-bf16 tensor GEMM: y = xh@Wh + xl@Wh + xh@Wlo
//   (mma.sync.m16n8k16 bf16 -> HMMA; tcgen05 unavailable: plain sm_103 target)
//   h = relu(LN( mean_{j in N(i)} yl[j] + bl + yr[i] ) * g + be)
// PADDED CSR (stride 64): one atomic-slot scatter; no count, no scan.
// y stored entirely FP16 (yl gathered randomly; yr streamed with .cs so the
// gather array stays L2-resident). agg: 1 node/warp, high occupancy.
// edge_index/batch are INT32. Launches only; static smem <= 48 KB.
// ---------------------------------------------------------------------------

#define NGRAPH 64
#define DEGS   64

// ------------------------- device scratch (static) -------------------------
__device__ __align__(16) __half g_ylh[50048 * 128];  // yl (random gather), fp16
__device__ __align__(16) __half g_yrh[50048 * 128];  // yr (streamed), fp16
__device__ __align__(16) float  g_h1 [50048 * 128];
__device__ __align__(16) float  g_h2 [50048 * 128];
__device__ int g_deg [50048];
__device__ int g_colp[50048 * DEGS];
// Weights in mma.sync B-FRAGMENT order (bf16 hi / lo residual):
// u = ((((k16*NT8 + ntile)*32 + lane)*2 + reg)*2 + elem)
__device__ __align__(16) __nv_bfloat16 g_wh0 [256 * 128];
__device__ __align__(16) __nv_bfloat16 g_wlo0[256 * 128];
__device__ __align__(16) __nv_bfloat16 g_wh1 [256 * 128];
__device__ __align__(16) __nv_bfloat16 g_wlo1[256 * 128];
__device__ __align__(16) __nv_bfloat16 g_wh2 [128 * 128];
__device__ __align__(16) __nv_bfloat16 g_wlo2[128 * 128];

// ------------------------------ small helpers ------------------------------
__device__ __forceinline__ uint32_t pack2bf(__nv_bfloat16 a, __nv_bfloat16 b) {
    __nv_bfloat162 t;
    t.x = a; t.y = b;
    return *reinterpret_cast<uint32_t*>(&t);
}

__device__ __forceinline__ void mma16816(float* d, const uint32_t* a,
                                         const uint32_t* b) {
    asm volatile(
        "mma.sync.aligned.m16n8k16.row.col.f32.bf16.bf16.f32 "
        "{%0,%1,%2,%3}, {%4,%5,%6,%7}, {%8,%9}, {%0,%1,%2,%3};"
        : "+f"(d[0]), "+f"(d[1]), "+f"(d[2]), "+f"(d[3])
        : "r"(a[0]), "r"(a[1]), "r"(a[2]), "r"(a[3]), "r"(b[0]), "r"(b[1]));
}

// ------------------------------ preprocessing ------------------------------
__global__ void scatter_pad_kernel(const int* __restrict__ ei, int E) {
    int e = blockIdx.x * blockDim.x + threadIdx.x;
    if (e < E) {
        int sN = ei[e];
        int d  = ei[E + e];
        int p  = atomicAdd(&g_deg[d], 1);
        if (p < DEGS) g_colp[d * DEGS + p] = sN;
    }
}

// All three weight splits in ONE kernel (+ zero g_deg).
__global__ void wconv_all_kernel(const float* __restrict__ Wl0, const float* __restrict__ Wr0,
                                 const float* __restrict__ Wl1, const float* __restrict__ Wr1,
                                 const float* __restrict__ Wl2, const float* __restrict__ Wr2) {
    for (int i = blockIdx.x * blockDim.x + threadIdx.x; i < 50048;
         i += gridDim.x * blockDim.x)
        g_deg[i] = 0;

    const int total = 32768 + 32768 + 16384;
    for (int idx = blockIdx.x * blockDim.x + threadIdx.x; idx < total;
         idx += gridDim.x * blockDim.x) {
        const float *Wl, *Wr;
        __nv_bfloat16 *WH, *WO;
        int off, F;
        if (idx < 32768)      { off = idx;          F = 128; Wl = Wl0; Wr = Wr0; WH = g_wh0; WO = g_wlo0; }
        else if (idx < 65536) { off = idx - 32768;  F = 128; Wl = Wl1; Wr = Wr1; WH = g_wh1; WO = g_wlo1; }
        else                  { off = idx - 65536;  F = 64;  Wl = Wl2; Wr = Wr2; WH = g_wh2; WO = g_wlo2; }
        int F2 = 2 * F, NT8 = F2 / 8;
        int o = off >> 7;
        int k = off & 127;
        float v = (o < F) ? Wl[o * 128 + k] : Wr[(o - F) * 128 + k];
        __nv_bfloat16 h = __float2bfloat16(v);
        __nv_bfloat16 l = __float2bfloat16(v - __bfloat162float(h));
        int k16 = k >> 4, kin = k & 15;
        int reg = kin >> 3, tq = (kin >> 1) & 3, elem = kin & 1;
        int lane = (o & 7) * 4 + tq;
        int u = ((((k16 * NT8 + (o >> 3)) * 32 + lane) * 2 + reg) * 2 + elem);
        WH[u] = h;
        WO[u] = l;
    }
}

// ---------------------- tensor-core dense GEMM (HMMA) ----------------------
template <int F2, int XSEL, int WSEL>
__global__ void __launch_bounds__(256) tgemm_kernel(const float* __restrict__ Xin,
                                                    int N) {
    constexpr int NT8 = F2 / 8;
    constexpr int WNT = F2 / 32;
    constexpr int F   = F2 / 2;
    constexpr int STR = 136;
    __shared__ __nv_bfloat16 xh[64 * STR];
    __shared__ __nv_bfloat16 xl[64 * STR];

    const float* X = (XSEL == 0) ? Xin : (XSEL == 1) ? g_h1 : g_h2;
    const uint32_t* WH = (const uint32_t*)((WSEL == 0) ? g_wh0  : (WSEL == 1) ? g_wh1  : g_wh2);
    const uint32_t* WO = (const uint32_t*)((WSEL == 0) ? g_wlo0 : (WSEL == 1) ? g_wlo1 : g_wlo2);

    const int tid  = threadIdx.x;
    const int w    = tid >> 5, lane = tid & 31;
    const int gid  = lane >> 2, tq = lane & 3;
    const int bm   = blockIdx.x * 64;
    const int wm   = (w >> 2) * 32;
    const int wn   = (w & 3) * (F2 / 4);
    const int wnt0 = wn >> 3;

#pragma unroll
    for (int i = 0; i < 8; i++) {
        int idx = tid + 256 * i;
        int m = idx >> 5, k4 = idx & 31;
        int row = bm + m;
        float4 v = make_float4(0.f, 0.f, 0.f, 0.f);
        if (row < N) v = *reinterpret_cast<const float4*>(X + (size_t)row * 128 + k4 * 4);
        __nv_bfloat16 h0 = __float2bfloat16(v.x), h1 = __float2bfloat16(v.y);
        __nv_bfloat16 h2 = __float2bfloat16(v.z), h3 = __float2bfloat16(v.w);
        __nv_bfloat16 l0 = __float2bfloat16(v.x - __bfloat162float(h0));
        __nv_bfloat16 l1 = __float2bfloat16(v.y - __bfloat162float(h1));
        __nv_bfloat16 l2 = __float2bfloat16(v.z - __bfloat162float(h2));
        __nv_bfloat16 l3 = __float2bfloat16(v.w - __bfloat162float(h3));
        int eo = m * STR + k4 * 4;
        *reinterpret_cast<uint2*>(&xh[eo]) = make_uint2(pack2bf(h0, h1), pack2bf(h2, h3));
        *reinterpret_cast<uint2*>(&xl[eo]) = make_uint2(pack2bf(l0, l1), pack2bf(l2, l3));
    }
    __syncthreads();

    float acc[2][WNT][4];
#pragma unroll
    for (int s = 0; s < 2; s++)
#pragma unroll
        for (int nt = 0; nt < WNT; nt++)
#pragma unroll
            for (int i = 0; i < 4; i++) acc[s][nt][i] = 0.f;

#pragma unroll
    for (int k16 = 0; k16 < 8; k16++) {
        const int c = k16 * 16 + tq * 2;
        uint32_t ah[2][4], al[2][4];
#pragma unroll
        for (int s = 0; s < 2; s++) {
            int base = (wm + s * 16 + gid) * STR + c;
            ah[s][0] = *reinterpret_cast<const uint32_t*>(&xh[base]);
            ah[s][1] = *reinterpret_cast<const uint32_t*>(&xh[base + 8 * STR]);
            ah[s][2] = *reinterpret_cast<const uint32_t*>(&xh[base + 8]);
            ah[s][3] = *reinterpret_cast<const uint32_t*>(&xh[base + 8 * STR + 8]);
            al[s][0] = *reinterpret_cast<const uint32_t*>(&xl[base]);
            al[s][1] = *reinterpret_cast<const uint32_t*>(&xl[base + 8 * STR]);
            al[s][2] = *reinterpret_cast<const uint32_t*>(&xl[base + 8]);
            al[s][3] = *reinterpret_cast<const uint32_t*>(&xl[base + 8 * STR + 8]);
        }
#pragma unroll
        for (int nt = 0; nt < WNT; nt++) {
            size_t base = ((size_t)(k16 * NT8 + wnt0 + nt) * 32 + lane) * 2;
            uint2 bh = *reinterpret_cast<const uint2*>(WH + base);
            uint2 bo = *reinterpret_cast<const uint2*>(WO + base);
            uint32_t bhv[2] = {bh.x, bh.y};
            uint32_t bov[2] = {bo.x, bo.y};
#pragma unroll
            for (int s = 0; s < 2; s++) {
                mma16816(acc[s][nt], ah[s], bhv);
                mma16816(acc[s][nt], al[s], bhv);
                mma16816(acc[s][nt], ah[s], bov);
            }
        }
    }

    // epilogue: both halves fp16; o0<F -> g_ylh else g_yrh
#pragma unroll
    for (int s = 0; s < 2; s++) {
        int r0 = bm + wm + s * 16 + gid;
#pragma unroll
        for (int nt = 0; nt < WNT; nt++) {
            int o0 = wn + nt * 8 + tq * 2;
            __half* dst = (o0 < F) ? (g_ylh + o0) : (g_yrh + o0 - F);
            if (r0 < N)
                *reinterpret_cast<__half2*>(dst + (size_t)r0 * F) =
                    __floats2half2_rn(acc[s][nt][0], acc[s][nt][1]);
            if (r0 + 8 < N)
                *reinterpret_cast<__half2*>(dst + (size_t)(r0 + 8) * F) =
                    __floats2half2_rn(acc[s][nt][2], acc[s][nt][3]);
        }
    }
}

// ------------------- fused aggregation + LayerNorm + ReLU -------------------
// One warp per node; fp16 gathers (.cg). Streaming operands (colp, yr) use
// .cs evict-first so the hot gather array g_ylh stays L2-resident.
// __launch_bounds__(256,6) caps regs (~42) for ~48 warps/SM latency cover.
template <int F, int OSEL>   // F: 128 or 64; OSEL: 1 -> g_h1, 2 -> g_h2
__global__ void __launch_bounds__(256, 6) agg_ln_kernel(const float* __restrict__ bl,
                                                        const float* __restrict__ gm,
                                                        const float* __restrict__ be,
                                                        int N) {
    constexpr int VPL = F / 32;        // floats per lane: 4 or 2
    float* Hout = (OSEL == 1) ? g_h1 : g_h2;
    int d    = (blockIdx.x * blockDim.x + threadIdx.x) >> 5;
    int lane = threadIdx.x & 31;
    if (d >= N) return;

    int deg = g_deg[d];
    int cap = min(deg, DEGS);

    float acc[4][VPL];
#pragma unroll
    for (int u = 0; u < 4; u++)
#pragma unroll
        for (int i = 0; i < VPL; i++) acc[u][i] = 0.f;

    const __half* Yl = g_ylh;
    for (int c0 = 0; c0 < cap; c0 += 32) {
        int j = 0;
        if (c0 + lane < cap) j = __ldcs(&g_colp[d * DEGS + c0 + lane]);
        int cnt = min(cap - c0, 32);
        int t = 0;
        for (; t + 4 <= cnt; t += 4) {
            int jj[4];
#pragma unroll
            for (int u = 0; u < 4; u++) jj[u] = __shfl_sync(0xffffffffu, j, t + u);
            if (VPL == 4) {
                uint2 q[4];
#pragma unroll
                for (int u = 0; u < 4; u++)
                    q[u] = __ldcg((const uint2*)(Yl + (size_t)jj[u] * F + lane * 4));
#pragma unroll
                for (int u = 0; u < 4; u++) {
                    float2 a = __half22float2(*(__half2*)&q[u].x);
                    float2 b = __half22float2(*(__half2*)&q[u].y);
                    acc[u][0] += a.x; acc[u][1] += a.y;
                    acc[u][2] += b.x; acc[u][3] += b.y;
                }
            } else {
                uint32_t q[4];
#pragma unroll
                for (int u = 0; u < 4; u++)
                    q[u] = __ldcg((const uint32_t*)(Yl + (size_t)jj[u] * F + lane * 2));
#pragma unroll
                for (int u = 0; u < 4; u++) {
                    float2 a = __half22float2(*(__half2*)&q[u]);
                    acc[u][0] += a.x; acc[u][1] += a.y;
                }
            }
        }
        for (; t < cnt; t++) {
            int jj = __shfl_sync(0xffffffffu, j, t);
            if (VPL == 4) {
                uint2 q = __ldcg((const uint2*)(Yl + (size_t)jj * F + lane * 4));
                float2 a = __half22float2(*(__half2*)&q.x);
                float2 b = __half22float2(*(__half2*)&q.y);
                acc[0][0] += a.x; acc[0][1] += a.y;
                acc[0][2] += b.x; acc[0][3] += b.y;
            } else {
                uint32_t q = __ldcg((const uint32_t*)(Yl + (size_t)jj * F + lane * 2));
                float2 a = __half22float2(*(__half2*)&q);
                acc[0][0] += a.x; acc[0][1] += a.y;
            }
        }
    }

    // yr (fp16, streamed evict-first) + bias, then LN + ReLU
    float invd = 1.0f / (float)max(deg, 1);
    float yrv[VPL];
    if (VPL == 4) {
        uint2 q = __ldcs((const uint2*)(g_yrh + (size_t)d * F + lane * 4));
        float2 a = __half22float2(*(__half2*)&q.x);
        float2 b = __half22float2(*(__half2*)&q.y);
        yrv[0] = a.x; yrv[1] = a.y; yrv[2] = b.x; yrv[3] = b.y;
    } else {
        uint32_t q = __ldcs((const uint32_t*)(g_yrh + (size_t)d * F + lane * 2));
        float2 a = __half22float2(*(__half2*)&q);
        yrv[0] = a.x; yrv[1] = a.y;
    }

    float v[VPL];
#pragma unroll
    for (int i = 0; i < VPL; i++) {
        float a = (acc[0][i] + acc[1][i]) + (acc[2][i] + acc[3][i]);
        v[i] = a * invd + yrv[i] + bl[lane * VPL + i];
    }

    float s = 0.f;
#pragma unroll
    for (int i = 0; i < VPL; i++) s += v[i];
#pragma unroll
    for (int off = 16; off > 0; off >>= 1) s += __shfl_xor_sync(0xffffffffu, s, off);
    float mu = s * (1.0f / F);

    float q = 0.f;
#pragma unroll
    for (int i = 0; i < VPL; i++) { float dd = v[i] - mu; q += dd * dd; }
#pragma unroll
    for (int off = 16; off > 0; off >>= 1) q += __shfl_xor_sync(0xffffffffu, q, off);
    float rstd = rsqrtf(q * (1.0f / F) + 1e-5f);

    float* out = Hout + (size_t)d * F + lane * VPL;
#pragma unroll
    for (int i = 0; i < VPL; i++) {
        float o = (v[i] - mu) * rstd * gm[lane * VPL + i] + be[lane * VPL + i];
        out[i] = fmaxf(o, 0.f);
    }
}

// ------------------ fused pooling (mean|max) + MLP head ---------------------
__device__ __forceinline__ int lbound32(const int* b, int n, int v) {
    int lo = 0, hi = n;
    while (lo < hi) {
        int mid = (lo + hi) >> 1;
        if (b[mid] < v) lo = mid + 1; else hi = mid;
    }
    return lo;
}

__global__ void poolhead_kernel(const int* __restrict__ batch,
                                const float* __restrict__ cW1, const float* __restrict__ cb1,
                                const float* __restrict__ cW2, const float* __restrict__ cb2,
                                float* __restrict__ out, int N) {
    int g = blockIdx.x;
    int s = lbound32(batch, N, g);
    int e = lbound32(batch, N, g + 1);
    int tid = threadIdx.x;
    int f = tid & 63;
    int r = tid >> 6;
    float sum = 0.f, mx = 0.f;
    for (int i = s + r; i < e; i += 4) {
        float v = g_h1[(size_t)i * 64 + f];
        sum += v;
        mx = fmaxf(mx, v);
    }
    __shared__ float ssum[4][64], smax[4][64], zs[128], s1[128];
    ssum[r][f] = sum;
    smax[r][f] = mx;
    __syncthreads();
    if (r == 0) {
        float S = ssum[0][f] + ssum[1][f] + ssum[2][f] + ssum[3][f];
        float M = fmaxf(fmaxf(smax[0][f], smax[1][f]), fmaxf(smax[2][f], smax[3][f]));
        float invc = 1.0f / (float)max(e - s, 1);
        zs[f]      = S * invc;
        zs[64 + f] = M;
    }
    __syncthreads();
    if (tid < 128) {
        float acc = cb1[tid];
        const float* w = cW1 + tid * 128;
#pragma unroll 8
        for (int k = 0; k < 128; k++) acc += zs[k] * w[k];
        s1[tid] = fmaxf(acc, 0.f);
    }
    __syncthreads();
    if (tid < 2) {
        float a = cb2[tid];
        const float* w2 = cW2 + tid * 128;
        for (int k = 0; k < 128; k++) a += s1[k] * w2[k];
        out[g * 2 + tid] = a;
    }
}

// --------------------------------- launcher ---------------------------------
extern "C" void kernel_launch(void* const* d_in, const int* in_sizes, int n_in,
                              void* d_out, int out_size) {
    const float* x     = (const float*)d_in[0];
    const int*   ei    = (const int*)d_in[1];
    const int*   batch = (const int*)d_in[2];
    const float *Wl0 = (const float*)d_in[3],  *bl0 = (const float*)d_in[4],
                *Wr0 = (const float*)d_in[5],  *g0  = (const float*)d_in[6],
                *be0 = (const float*)d_in[7];
    const float *Wl1 = (const float*)d_in[8],  *bl1 = (const float*)d_in[9],
                *Wr1 = (const float*)d_in[10], *g1  = (const float*)d_in[11],
                *be1 = (const float*)d_in[12];
    const float *Wl2 = (const float*)d_in[13], *bl2 = (const float*)d_in[14],
                *Wr2 = (const float*)d_in[15], *g2  = (const float*)d_in[16],
                *be2 = (const float*)d_in[17];
    const float *cW1 = (const float*)d_in[18], *cb1 = (const float*)d_in[19],
                *cW2 = (const float*)d_in[20], *cb2 = (const float*)d_in[21];
    float* out = (float*)d_out;

    const int N = in_sizes[0] / 128;
    const int E = in_sizes[1] / 2;

    const int tgGrid  = (N + 63) / 64;
    const int aggGrid = (N + 7) / 8;      // 1 node/warp, 8 warps/block

    wconv_all_kernel<<<320, 256>>>(Wl0, Wr0, Wl1, Wr1, Wl2, Wr2);
    scatter_pad_kernel<<<(E + 255) / 256, 256>>>(ei, E);
    tgemm_kernel<256, 0, 0><<<tgGrid, 256>>>(x, N);

    agg_ln_kernel<128, 1><<<aggGrid, 256>>>(bl0, g0, be0, N);

    tgemm_kernel<256, 1, 1><<<tgGrid, 256>>>(nullptr, N);
    agg_ln_kernel<128, 2><<<aggGrid, 256>>>(bl1, g1, be1, N);

    tgemm_kernel<128, 2, 2><<<tgGrid, 256>>>(nullptr, N);
    agg_ln_kernel<64, 1><<<aggGrid, 256>>>(bl2, g2, be2, N);

    poolhead_kernel<<<NGRAPH, 256>>>(batch, cW1, cb1, cW2, cb2, out, N);
}